// round 11
// baseline (speedup 1.0000x reference)
#include <cuda_runtime.h>
#include <cuda_fp16.h>
#include <math.h>
#include <stdint.h>

#define N_NODE 80000
#define N_NET  20000
#define NEDGE  150000
#define HD     32
#define HE     16

#define TILE_M 128
#define NTILES ((NEDGE + TILE_M - 1) / TILE_M)   // 1172
#define GRIDX  222                                // x2 relations = 444 CTAs = 148 SMs * 3
#define NFRAG  (HD * 4 * 32)                      // 4096 fragment slots

// smem layout (bytes)
#define NF_STRIDE 33
#define NF_BYTES  (TILE_M * NF_STRIDE * 4)        // 16896 (u32 half2-dup per element)
#define FH_OFF    NF_BYTES
#define SM_TOT    (NF_BYTES + NFRAG * 8)          // 49664

typedef unsigned int u32;

// ---------------- helpers ----------------
__device__ __forceinline__ u32 f16pair(float lo, float hi) {
    __half2 h = __floats2half2_rn(lo, hi);        // x=lo, y=hi
    return *reinterpret_cast<u32*>(&h);
}
__device__ __forceinline__ u32 half2dup(float v) {
    __half h = __float2half_rn(v);
    u32 hu = *reinterpret_cast<unsigned short*>(&h);
    return hu | (hu << 16);
}
__device__ __forceinline__ u32 hmul2u(u32 a, u32 b) {
    __half2 r = __hmul2(*reinterpret_cast<__half2*>(&a), *reinterpret_cast<__half2*>(&b));
    return *reinterpret_cast<u32*>(&r);
}
__device__ __forceinline__ void mma_f16(float* d, u32 a0, u32 a1, u32 a2, u32 a3,
                                        u32 b0, u32 b1) {
    asm volatile(
        "mma.sync.aligned.m16n8k16.row.col.f32.f16.f16.f32 "
        "{%0,%1,%2,%3}, {%4,%5,%6,%7}, {%8,%9}, {%0,%1,%2,%3};"
        : "+f"(d[0]), "+f"(d[1]), "+f"(d[2]), "+f"(d[3])
        : "r"(a0), "r"(a1), "r"(a2), "r"(a3), "r"(b0), "r"(b1));
}
__device__ __forceinline__ void red_v2(float* p, float a, float b) {
    asm volatile("red.global.add.v2.f32 [%0], {%1, %2};"
                 :: "l"(p), "f"(a), "f"(b) : "memory");
}
__device__ __forceinline__ void red_v4(float* p, float a, float b, float c, float d) {
    asm volatile("red.global.add.v4.f32 [%0], {%1, %2, %3, %4};"
                 :: "l"(p), "f"(a), "f"(b), "f"(c), "f"(d) : "memory");
}

// ---- scratch (device globals; no allocation allowed) ----
__device__ float g_deg_out[N_NODE];
__device__ float g_deg_in [N_NET];
__device__ float g_deg_p  [N_NODE];
__device__ float g_deg_n  [N_NODE];
__device__ __align__(16) float g_agg [N_NET * HD];
__device__ __align__(16) float g_accp[N_NODE * HD];
__device__ __align__(16) float g_accn[N_NODE * HD];
__device__ float g_btp [N_NET  * HD];
__device__ float g_btn [N_NODE * HD];
__device__ __align__(16) uint2 g_fh_p[NFRAG];   // interleaved: ((i*32+lane)*4 + nb)
__device__ __align__(16) uint2 g_fh_n[NFRAG];

// ---------------------------------------------------------------------------
__global__ void k_zero() {
    int stride = gridDim.x * blockDim.x;
    int i0 = blockIdx.x * blockDim.x + threadIdx.x;
    const float4 z = make_float4(0.f, 0.f, 0.f, 0.f);
    for (int j = i0; j < N_NODE / 4; j += stride) {
        reinterpret_cast<float4*>(g_deg_out)[j] = z;
        reinterpret_cast<float4*>(g_deg_p)[j] = z;
        reinterpret_cast<float4*>(g_deg_n)[j] = z;
    }
    for (int j = i0; j < N_NET / 4; j += stride) reinterpret_cast<float4*>(g_deg_in)[j] = z;
    for (int j = i0; j < N_NET * HD / 4; j += stride) reinterpret_cast<float4*>(g_agg)[j] = z;
    for (int j = i0; j < N_NODE * HD / 4; j += stride) {
        reinterpret_cast<float4*>(g_accp)[j] = z;
        reinterpret_cast<float4*>(g_accn)[j] = z;
    }
}

// ---------------------------------------------------------------------------
__global__ void k_deg(const int* __restrict__ ps, const int* __restrict__ pd,
                      const int* __restrict__ pnd, const int* __restrict__ nrd) {
    int e = blockIdx.x * blockDim.x + threadIdx.x;
    if (e >= NEDGE) return;
    atomicAdd(&g_deg_out[ps[e]],  1.f);
    atomicAdd(&g_deg_in [pd[e]],  1.f);
    atomicAdd(&g_deg_p  [pnd[e]], 1.f);
    atomicAdd(&g_deg_n  [nrd[e]], 1.f);
}

// ---------------------------------------------------------------------------
// pins aggregation with vector reductions: one thread per (edge, quarter-row)
__global__ void k_pins(const float* __restrict__ nodef,
                       const int* __restrict__ src, const int* __restrict__ dst) {
    int t = blockIdx.x * blockDim.x + threadIdx.x;
    if (t >= NEDGE * 8) return;
    int e = t >> 3, q = t & 7;
    int s = src[e];
    float nrm = rsqrtf(fmaxf(g_deg_out[s], 1.f));
    float4 v = reinterpret_cast<const float4*>(nodef + (size_t)s * HD)[q];
    red_v4(g_agg + (size_t)dst[e] * HD + q * 4,
           v.x * nrm, v.y * nrm, v.z * nrm, v.w * nrm);
}

// ---------------------------------------------------------------------------
__global__ void k_netout(const float* __restrict__ gcw, const float* __restrict__ gcb,
                         float* __restrict__ out) {
    int t = blockIdx.x * blockDim.x + threadIdx.x;
    if (t >= N_NET * HD) return;
    int n = t >> 5, o = t & 31;
    float nrm = rsqrtf(fmaxf(g_deg_in[n], 1.f));
    float a = 0.f;
    #pragma unroll
    for (int d = 0; d < HD; d++)
        a = fmaf(g_agg[n * HD + d], gcw[d * HD + o], a);
    out[(size_t)N_NODE * HD + t] = a * nrm + gcb[o];
}

// ---------------------------------------------------------------------------
// Precompute fp16 B fragments, nb-interleaved layout: slot = (i*32+lane)*4 + nb
// so each lane's 4 nb-fragments are 32 contiguous bytes (2x LDS.128 per i).
__global__ void k_wprep(const float* __restrict__ w0, const float* __restrict__ w1,
                        uint2* __restrict__ fh0, uint2* __restrict__ fh1) {
    int gidx = blockIdx.x * blockDim.x + threadIdx.x;
    if (gidx >= 2 * NFRAG) return;
    int rel = gidx >= NFRAG;
    int idx = gidx - rel * NFRAG;
    const float* w = rel ? w1 : w0;
    uint2* fh = rel ? fh1 : fh0;
    int nb = idx & 3, lane = (idx >> 2) & 31, i = idx >> 7;
    int o = nb * 8 + (lane >> 2);
    int k0 = (lane & 3) * 2;
    const float* row = w + ((size_t)i * HD + o) * HE;
    fh[idx] = make_uint2(f16pair(row[k0],     row[k0 + 1]),
                         f16pair(row[k0 + 8], row[k0 + 9]));
}

// ---------------------------------------------------------------------------
// Exact bias term tables for both relations in one launch.
__global__ void k_bterm(const float* __restrict__ netf, const float* __restrict__ tb,
                        const float* __restrict__ nodef, const float* __restrict__ gb) {
    int t = blockIdx.x * blockDim.x + threadIdx.x;
    if (t >= (N_NET + N_NODE) * HD) return;
    const float* feat; const float* b; float* out; int row;
    if (t < N_NET * HD) {
        feat = netf; b = tb; out = g_btp; row = t >> 5;
    } else {
        t -= N_NET * HD;
        feat = nodef; b = gb; out = g_btn; row = t >> 5;
    }
    int o = t & 31;
    float a = 0.f;
    #pragma unroll
    for (int i = 0; i < HD; i++)
        a = fmaf(feat[(size_t)row * HD + i], b[i * HD + o], a);
    out[(size_t)row * HD + o] = a;
}

// ---------------------------------------------------------------------------
// Fused NNConv, single-pass fp16 with HMUL2 A-fragments.
// nf stored as duplicated half2 in smem; pf pre-packed half2 per tile.
__global__ void __launch_bounds__(256, 3)
k_nnconv_mma(const float* __restrict__ sf0, const float* __restrict__ ef0,
             const int* __restrict__ src0, const int* __restrict__ dst0,
             const uint2* __restrict__ gfh0, const float* __restrict__ bt0,
             float* __restrict__ acc0,
             const float* __restrict__ sf1, const float* __restrict__ ef1,
             const int* __restrict__ src1, const int* __restrict__ dst1,
             const uint2* __restrict__ gfh1, const float* __restrict__ bt1,
             float* __restrict__ acc1) {
    extern __shared__ char smem[];
    u32* nf_s = (u32*)smem;                        // half2-dup per (row, i)
    uint2* fh_s = (uint2*)(smem + FH_OFF);
    int tid = threadIdx.x;
    int rel = blockIdx.y;

    const float* srcfeat = rel ? sf1 : sf0;
    const float* efeat   = rel ? ef1 : ef0;
    const int* src       = rel ? src1 : src0;
    const int* dst       = rel ? dst1 : dst0;
    const uint2* gfh     = rel ? gfh1 : gfh0;
    const float* bterm   = rel ? bt1 : bt0;
    float* acc           = rel ? acc1 : acc0;

    // copy B fragments (32 KB) into smem once
    {
        const uint4* s1 = (const uint4*)gfh;
        uint4* d1 = (uint4*)fh_s;
        #pragma unroll
        for (int q = 0; q < (NFRAG * 8 / 16) / 256; q++)
            d1[q * 256 + tid] = s1[q * 256 + tid];
    }

    int lane = tid & 31, wid = tid >> 5;
    int r0 = lane >> 2, c0 = (lane & 3) * 2;
    int wr = wid * 16;

    #pragma unroll 1
    for (int tile = blockIdx.x; tile < NTILES; tile += GRIDX) {
        int base = tile * TILE_M;

        __syncthreads();   // protect nf_s reuse (and fragment copy on first iter)
        for (int idx = tid; idx < TILE_M * HD; idx += 256) {
            int row = idx >> 5, col = idx & 31;
            int e = base + row;
            float v = 0.f;
            if (e < NEDGE) v = srcfeat[(size_t)src[e] * HD + col];
            nf_s[row * NF_STRIDE + col] = half2dup(v);
        }
        __syncthreads();

        int e0 = base + wr + r0;
        int e1 = e0 + 8;
        bool l0 = (e0 < NEDGE), l1 = (e1 < NEDGE);

        u32 pf0a = 0, pf0b = 0, pf1a = 0, pf1b = 0;   // half2 {pf[c0],pf[c0+1]}, {+8}
        if (l0) {
            float2 q = *(const float2*)(efeat + (size_t)e0 * HE + c0);
            pf0a = f16pair(q.x, q.y);
            q = *(const float2*)(efeat + (size_t)e0 * HE + c0 + 8);
            pf0b = f16pair(q.x, q.y);
        }
        if (l1) {
            float2 q = *(const float2*)(efeat + (size_t)e1 * HE + c0);
            pf1a = f16pair(q.x, q.y);
            q = *(const float2*)(efeat + (size_t)e1 * HE + c0 + 8);
            pf1b = f16pair(q.x, q.y);
        }

        float d[4][4];
        #pragma unroll
        for (int nb = 0; nb < 4; nb++)
            #pragma unroll
            for (int q = 0; q < 4; q++) d[nb][q] = 0.f;

        #pragma unroll 4
        for (int i = 0; i < HD; i++) {
            u32 f0d = nf_s[(wr + r0) * NF_STRIDE + i];
            u32 f1d = nf_s[(wr + r0 + 8) * NF_STRIDE + i];
            u32 ah0 = hmul2u(f0d, pf0a);
            u32 ah1 = hmul2u(f1d, pf1a);
            u32 ah2 = hmul2u(f0d, pf0b);
            u32 ah3 = hmul2u(f1d, pf1b);
            const uint4* bp = (const uint4*)(fh_s + (i * 32 + lane) * 4);
            uint4 b01 = bp[0];
            uint4 b23 = bp[1];
            mma_f16(d[0], ah0, ah1, ah2, ah3, b01.x, b01.y);
            mma_f16(d[1], ah0, ah1, ah2, ah3, b01.z, b01.w);
            mma_f16(d[2], ah0, ah1, ah2, ah3, b23.x, b23.y);
            mma_f16(d[3], ah0, ah1, ah2, ah3, b23.z, b23.w);
        }

        if (l0) {
            int s0 = src[e0], dn0 = dst[e0];
            const float* bt = bterm + (size_t)s0 * HD;
            float* ap = acc + (size_t)dn0 * HD;
            #pragma unroll
            for (int nb = 0; nb < 4; nb++) {
                int o = nb * 8 + c0;
                red_v2(ap + o, d[nb][0] + bt[o], d[nb][1] + bt[o + 1]);
            }
        }
        if (l1) {
            int s1i = src[e1], dn1 = dst[e1];
            const float* bt = bterm + (size_t)s1i * HD;
            float* ap = acc + (size_t)dn1 * HD;
            #pragma unroll
            for (int nb = 0; nb < 4; nb++) {
                int o = nb * 8 + c0;
                red_v2(ap + o, d[nb][2] + bt[o], d[nb][3] + bt[o + 1]);
            }
        }
    }
}

// ---------------------------------------------------------------------------
__global__ void k_final(const float* __restrict__ pb, const float* __restrict__ nb,
                        float* __restrict__ out) {
    int t = blockIdx.x * blockDim.x + threadIdx.x;
    if (t >= N_NODE * HD) return;
    int n = t >> 5, o = t & 31;
    float p = g_accp[t] / fmaxf(g_deg_p[n], 1.f) + pb[o];
    float q = g_accn[t] / fmaxf(g_deg_n[n], 1.f) + nb[o];
    out[t] = fmaxf(p, q);
}

// ---------------------------------------------------------------------------
extern "C" void kernel_launch(void* const* d_in, const int* in_sizes, int n_in,
                              void* d_out, int out_size) {
    const float* node_feat = (const float*)d_in[0];
    const float* net_feat  = (const float*)d_in[1];
    const float* pin_feat  = (const float*)d_in[2];
    const float* edge_feat = (const float*)d_in[3];
    const float* topo_w    = (const float*)d_in[4];
    const float* topo_b    = (const float*)d_in[5];
    const float* geom_w    = (const float*)d_in[6];
    const float* geom_b    = (const float*)d_in[7];
    const float* gc_w      = (const float*)d_in[8];
    const float* gc_b      = (const float*)d_in[9];
    const float* pinned_b  = (const float*)d_in[10];
    const float* near_b    = (const float*)d_in[11];
    const int* pins_src    = (const int*)d_in[12];
    const int* pins_dst    = (const int*)d_in[13];
    const int* pinned_src  = (const int*)d_in[14];
    const int* pinned_dst  = (const int*)d_in[15];
    const int* near_src    = (const int*)d_in[16];
    const int* near_dst    = (const int*)d_in[17];
    float* out = (float*)d_out;

    cudaFuncSetAttribute(k_nnconv_mma, cudaFuncAttributeMaxDynamicSharedMemorySize, SM_TOT);

    float *accp, *accn, *btp, *btn;
    uint2 *fhp, *fhn;
    cudaGetSymbolAddress((void**)&accp, g_accp);
    cudaGetSymbolAddress((void**)&accn, g_accn);
    cudaGetSymbolAddress((void**)&btp,  g_btp);
    cudaGetSymbolAddress((void**)&btn,  g_btn);
    cudaGetSymbolAddress((void**)&fhp,  g_fh_p);
    cudaGetSymbolAddress((void**)&fhn,  g_fh_n);

    // Fork-join concurrency: side stream runs the pins-relation chain while the
    // origin stream runs the NNConv chain.
    cudaStream_t s2;
    cudaStreamCreateWithFlags(&s2, cudaStreamNonBlocking);
    cudaEvent_t evFork, evZero, evDeg, evJoin;
    cudaEventCreateWithFlags(&evFork, cudaEventDisableTiming);
    cudaEventCreateWithFlags(&evZero, cudaEventDisableTiming);
    cudaEventCreateWithFlags(&evDeg,  cudaEventDisableTiming);
    cudaEventCreateWithFlags(&evJoin, cudaEventDisableTiming);

    cudaEventRecord(evFork, 0);
    cudaStreamWaitEvent(s2, evFork, 0);

    // --- side stream: zero + degrees + pins relation ---
    k_zero<<<512, 256, 0, s2>>>();
    cudaEventRecord(evZero, s2);
    k_deg<<<(NEDGE + 255) / 256, 256, 0, s2>>>(pins_src, pins_dst, pinned_dst, near_dst);
    cudaEventRecord(evDeg, s2);
    k_pins<<<(NEDGE * 8 + 255) / 256, 256, 0, s2>>>(node_feat, pins_src, pins_dst);
    k_netout<<<(N_NET * HD + 255) / 256, 256, 0, s2>>>(gc_w, gc_b, out);
    cudaEventRecord(evJoin, s2);

    // --- origin stream: fragment/bias prep + NNConv + final ---
    k_wprep<<<(2 * NFRAG + 255) / 256, 256>>>(topo_w, geom_w, fhp, fhn);
    k_bterm<<<((N_NET + N_NODE) * HD + 255) / 256, 256>>>(net_feat, topo_b,
                                                          node_feat, geom_b);
    cudaStreamWaitEvent(0, evZero, 0);   // acc buffers zeroed
    dim3 grid(GRIDX, 2);
    k_nnconv_mma<<<grid, 256, SM_TOT>>>(net_feat,  pin_feat,  pinned_src, pinned_dst,
                                        fhp, btp, accp,
                                        node_feat, edge_feat, near_src,  near_dst,
                                        fhn, btn, accn);
    cudaStreamWaitEvent(0, evDeg, 0);    // g_deg_p / g_deg_n ready
    k_final<<<(N_NODE * HD + 255) / 256, 256>>>(pinned_b, near_b, out);
    cudaStreamWaitEvent(0, evJoin, 0);   // join side stream (net_out part of out)
}

// round 12
// speedup vs baseline: 1.1044x; 1.1044x over previous
#include <cuda_runtime.h>
#include <cuda_fp16.h>
#include <math.h>
#include <stdint.h>

#define N_NODE 80000
#define N_NET  20000
#define NEDGE  150000
#define HD     32
#define HE     16

#define TILE_M 128
#define NTILES ((NEDGE + TILE_M - 1) / TILE_M)   // 1172
#define GRIDX  222                                // x2 relations = 444 CTAs = 148 SMs * 3
#define NFRAG  (HD * 4 * 32)                      // 4096 fragment slots (i, nb, lane)

// smem layout (bytes)
#define NF_STRIDE 33
#define NF_BYTES  (TILE_M * NF_STRIDE * 4)        // 16896 (16-aligned)
#define FH_OFF    NF_BYTES
#define SM_TOT    (NF_BYTES + NFRAG * 8)          // 49664

typedef unsigned int u32;

// ---------------- helpers ----------------
__device__ __forceinline__ u32 f16pair(float lo, float hi) {
    __half2 h = __floats2half2_rn(lo, hi);        // x=lo, y=hi
    return *reinterpret_cast<u32*>(&h);
}
__device__ __forceinline__ void mma_f16(float* d, u32 a0, u32 a1, u32 a2, u32 a3,
                                        u32 b0, u32 b1) {
    asm volatile(
        "mma.sync.aligned.m16n8k16.row.col.f32.f16.f16.f32 "
        "{%0,%1,%2,%3}, {%4,%5,%6,%7}, {%8,%9}, {%0,%1,%2,%3};"
        : "+f"(d[0]), "+f"(d[1]), "+f"(d[2]), "+f"(d[3])
        : "r"(a0), "r"(a1), "r"(a2), "r"(a3), "r"(b0), "r"(b1));
}
__device__ __forceinline__ void red_v4(float* p, float a, float b, float c, float d) {
    asm volatile("red.global.add.v4.f32 [%0], {%1, %2, %3, %4};"
                 :: "l"(p), "f"(a), "f"(b), "f"(c), "f"(d) : "memory");
}

// ---- scratch (device globals; no allocation allowed) ----
__device__ float g_deg_out[N_NODE];
__device__ float g_deg_in [N_NET];
__device__ float g_deg_p  [N_NODE];
__device__ float g_deg_n  [N_NODE];
__device__ __align__(16) float g_agg [N_NET * HD];
__device__ __align__(16) float g_accp[N_NODE * HD];
__device__ __align__(16) float g_accn[N_NODE * HD];
__device__ __align__(16) float g_btp [N_NET  * HD];
__device__ __align__(16) float g_btn [N_NODE * HD];
__device__ __align__(16) uint2 g_fh_p[NFRAG];
__device__ __align__(16) uint2 g_fh_n[NFRAG];

// ---------------------------------------------------------------------------
__global__ void k_zero() {
    int stride = gridDim.x * blockDim.x;
    int i0 = blockIdx.x * blockDim.x + threadIdx.x;
    const float4 z = make_float4(0.f, 0.f, 0.f, 0.f);
    for (int j = i0; j < N_NODE / 4; j += stride) {
        reinterpret_cast<float4*>(g_deg_out)[j] = z;
        reinterpret_cast<float4*>(g_deg_p)[j] = z;
        reinterpret_cast<float4*>(g_deg_n)[j] = z;
    }
    for (int j = i0; j < N_NET / 4; j += stride) reinterpret_cast<float4*>(g_deg_in)[j] = z;
    for (int j = i0; j < N_NET * HD / 4; j += stride) reinterpret_cast<float4*>(g_agg)[j] = z;
    for (int j = i0; j < N_NODE * HD / 4; j += stride) {
        reinterpret_cast<float4*>(g_accp)[j] = z;
        reinterpret_cast<float4*>(g_accn)[j] = z;
    }
}

// ---------------------------------------------------------------------------
__global__ void k_deg(const int* __restrict__ ps, const int* __restrict__ pd,
                      const int* __restrict__ pnd, const int* __restrict__ nrd) {
    int e = blockIdx.x * blockDim.x + threadIdx.x;
    if (e >= NEDGE) return;
    atomicAdd(&g_deg_out[ps[e]],  1.f);
    atomicAdd(&g_deg_in [pd[e]],  1.f);
    atomicAdd(&g_deg_p  [pnd[e]], 1.f);
    atomicAdd(&g_deg_n  [nrd[e]], 1.f);
}

// ---------------------------------------------------------------------------
// pins aggregation with vector reductions: one thread per (edge, quarter-row)
__global__ void k_pins(const float* __restrict__ nodef,
                       const int* __restrict__ src, const int* __restrict__ dst) {
    int t = blockIdx.x * blockDim.x + threadIdx.x;
    if (t >= NEDGE * 8) return;
    int e = t >> 3, q = t & 7;
    int s = src[e];
    float nrm = rsqrtf(fmaxf(g_deg_out[s], 1.f));
    float4 v = reinterpret_cast<const float4*>(nodef + (size_t)s * HD)[q];
    red_v4(g_agg + (size_t)dst[e] * HD + q * 4,
           v.x * nrm, v.y * nrm, v.z * nrm, v.w * nrm);
}

// ---------------------------------------------------------------------------
__global__ void k_netout(const float* __restrict__ gcw, const float* __restrict__ gcb,
                         float* __restrict__ out) {
    int t = blockIdx.x * blockDim.x + threadIdx.x;
    if (t >= N_NET * HD) return;
    int n = t >> 5, o = t & 31;
    float nrm = rsqrtf(fmaxf(g_deg_in[n], 1.f));
    float a = 0.f;
    #pragma unroll
    for (int d = 0; d < HD; d++)
        a = fmaf(g_agg[n * HD + d], gcw[d * HD + o], a);
    out[(size_t)N_NODE * HD + t] = a * nrm + gcb[o];
}

// ---------------------------------------------------------------------------
// Precompute fp16 B fragments for BOTH relations (m16n8k16 .col layout).
// R10 layout: slot = (i*4+nb)*32 + lane  (lane stride 8 B -> conflict-free LDS.64)
__global__ void k_wprep(const float* __restrict__ w0, const float* __restrict__ w1,
                        uint2* __restrict__ fh0, uint2* __restrict__ fh1) {
    int gidx = blockIdx.x * blockDim.x + threadIdx.x;
    if (gidx >= 2 * NFRAG) return;
    int rel = gidx >= NFRAG;
    int idx = gidx - rel * NFRAG;
    const float* w = rel ? w1 : w0;
    uint2* fh = rel ? fh1 : fh0;
    int lane = idx & 31, nb = (idx >> 5) & 3, i = idx >> 7;
    int o = nb * 8 + (lane >> 2);
    int k0 = (lane & 3) * 2;
    const float* row = w + ((size_t)i * HD + o) * HE;
    fh[idx] = make_uint2(f16pair(row[k0],     row[k0 + 1]),
                         f16pair(row[k0 + 8], row[k0 + 9]));
}

// ---------------------------------------------------------------------------
// Exact bias term tables for both relations in one launch.
__global__ void k_bterm(const float* __restrict__ netf, const float* __restrict__ tb,
                        const float* __restrict__ nodef, const float* __restrict__ gb) {
    int t = blockIdx.x * blockDim.x + threadIdx.x;
    if (t >= (N_NET + N_NODE) * HD) return;
    const float* feat; const float* b; float* out; int row;
    if (t < N_NET * HD) {
        feat = netf; b = tb; out = g_btp; row = t >> 5;
    } else {
        t -= N_NET * HD;
        feat = nodef; b = gb; out = g_btn; row = t >> 5;
    }
    int o = t & 31;
    float a = 0.f;
    #pragma unroll
    for (int i = 0; i < HD; i++)
        a = fmaf(feat[(size_t)row * HD + i], b[i * HD + o], a);
    out[(size_t)row * HD + o] = a;
}

// ---------------------------------------------------------------------------
// Fused NNConv, single-pass fp16: D = Zh@Wh (z computed fp32, one rounding).
// Persistent grid-stride over tiles; blockIdx.y selects relation.
// Epilogue: lane pairs combine via shfl_xor(1) -> even lanes issue red.v4
// (halves RED lanes) with bias quads loaded as LDG.128.
__global__ void __launch_bounds__(256, 3)
k_nnconv_mma(const float* __restrict__ sf0, const float* __restrict__ ef0,
             const int* __restrict__ src0, const int* __restrict__ dst0,
             const uint2* __restrict__ gfh0, const float* __restrict__ bt0,
             float* __restrict__ acc0,
             const float* __restrict__ sf1, const float* __restrict__ ef1,
             const int* __restrict__ src1, const int* __restrict__ dst1,
             const uint2* __restrict__ gfh1, const float* __restrict__ bt1,
             float* __restrict__ acc1) {
    extern __shared__ char smem[];
    float* nf_s = (float*)smem;
    uint2* fh_s = (uint2*)(smem + FH_OFF);
    int tid = threadIdx.x;
    int rel = blockIdx.y;

    const float* srcfeat = rel ? sf1 : sf0;
    const float* efeat   = rel ? ef1 : ef0;
    const int* src       = rel ? src1 : src0;
    const int* dst       = rel ? dst1 : dst0;
    const uint2* gfh     = rel ? gfh1 : gfh0;
    const float* bterm   = rel ? bt1 : bt0;
    float* acc           = rel ? acc1 : acc0;

    // copy B fragments (32 KB) into smem once
    {
        const uint4* s1 = (const uint4*)gfh;
        uint4* d1 = (uint4*)fh_s;
        #pragma unroll
        for (int q = 0; q < (NFRAG * 8 / 16) / 256; q++)
            d1[q * 256 + tid] = s1[q * 256 + tid];
    }

    int lane = tid & 31, wid = tid >> 5;
    int r0 = lane >> 2, c0 = (lane & 3) * 2;
    int wr = wid * 16;
    bool evenlane = ((lane & 1) == 0);
    int q0 = (lane & 3) * 2;        // 0,2,4,6 ; even lanes have q0 in {0,4}

    #pragma unroll 1
    for (int tile = blockIdx.x; tile < NTILES; tile += GRIDX) {
        int base = tile * TILE_M;

        __syncthreads();   // protect nf_s reuse (and fragment copy on first iter)
        for (int idx = tid; idx < TILE_M * HD; idx += 256) {
            int row = idx >> 5, col = idx & 31;
            int e = base + row;
            float v = 0.f;
            if (e < NEDGE) v = srcfeat[(size_t)src[e] * HD + col];
            nf_s[row * NF_STRIDE + col] = v;
        }
        __syncthreads();

        int e0 = base + wr + r0;
        int e1 = e0 + 8;
        bool l0 = (e0 < NEDGE), l1 = (e1 < NEDGE);

        float pf0[4] = {0.f, 0.f, 0.f, 0.f}, pf1[4] = {0.f, 0.f, 0.f, 0.f};
        if (l0) {
            float2 q = *(const float2*)(efeat + (size_t)e0 * HE + c0);
            pf0[0] = q.x; pf0[1] = q.y;
            q = *(const float2*)(efeat + (size_t)e0 * HE + c0 + 8);
            pf0[2] = q.x; pf0[3] = q.y;
        }
        if (l1) {
            float2 q = *(const float2*)(efeat + (size_t)e1 * HE + c0);
            pf1[0] = q.x; pf1[1] = q.y;
            q = *(const float2*)(efeat + (size_t)e1 * HE + c0 + 8);
            pf1[2] = q.x; pf1[3] = q.y;
        }

        float d[4][4];
        #pragma unroll
        for (int nb = 0; nb < 4; nb++)
            #pragma unroll
            for (int q = 0; q < 4; q++) d[nb][q] = 0.f;

        #pragma unroll 4
        for (int i = 0; i < HD; i++) {
            float f0 = nf_s[(wr + r0) * NF_STRIDE + i];
            float f1 = nf_s[(wr + r0 + 8) * NF_STRIDE + i];
            u32 ah0 = f16pair(f0 * pf0[0], f0 * pf0[1]);
            u32 ah1 = f16pair(f1 * pf1[0], f1 * pf1[1]);
            u32 ah2 = f16pair(f0 * pf0[2], f0 * pf0[3]);
            u32 ah3 = f16pair(f1 * pf1[2], f1 * pf1[3]);
            #pragma unroll
            for (int nb = 0; nb < 4; nb++) {
                uint2 bh = fh_s[(i * 4 + nb) * 32 + lane];
                mma_f16(d[nb], ah0, ah1, ah2, ah3, bh.x, bh.y);
            }
        }

        // epilogue: pair lanes (lane, lane^1) -> even lane writes red.v4 of 4 cols
        if (l0) {
            int s0 = src[e0], dn0 = dst[e0];
            const float* bt = bterm + (size_t)s0 * HD;
            float* ap = acc + (size_t)dn0 * HD;
            #pragma unroll
            for (int nb = 0; nb < 4; nb++) {
                float p0 = __shfl_xor_sync(0xffffffffu, d[nb][0], 1);
                float p1 = __shfl_xor_sync(0xffffffffu, d[nb][1], 1);
                if (evenlane) {
                    int o = nb * 8 + q0;            // multiple of 4
                    float4 bq = *(const float4*)(bt + o);
                    red_v4(ap + o, d[nb][0] + bq.x, d[nb][1] + bq.y,
                                   p0 + bq.z,       p1 + bq.w);
                }
            }
        }
        if (l1) {
            int s1i = src[e1], dn1 = dst[e1];
            const float* bt = bterm + (size_t)s1i * HD;
            float* ap = acc + (size_t)dn1 * HD;
            #pragma unroll
            for (int nb = 0; nb < 4; nb++) {
                float p2 = __shfl_xor_sync(0xffffffffu, d[nb][2], 1);
                float p3 = __shfl_xor_sync(0xffffffffu, d[nb][3], 1);
                if (evenlane) {
                    int o = nb * 8 + q0;
                    float4 bq = *(const float4*)(bt + o);
                    red_v4(ap + o, d[nb][2] + bq.x, d[nb][3] + bq.y,
                                   p2 + bq.z,       p3 + bq.w);
                }
            }
        }
    }
}

// ---------------------------------------------------------------------------
__global__ void k_final(const float* __restrict__ pb, const float* __restrict__ nb,
                        float* __restrict__ out) {
    int t = blockIdx.x * blockDim.x + threadIdx.x;
    if (t >= N_NODE * HD) return;
    int n = t >> 5, o = t & 31;
    float p = g_accp[t] / fmaxf(g_deg_p[n], 1.f) + pb[o];
    float q = g_accn[t] / fmaxf(g_deg_n[n], 1.f) + nb[o];
    out[t] = fmaxf(p, q);
}

// ---------------------------------------------------------------------------
extern "C" void kernel_launch(void* const* d_in, const int* in_sizes, int n_in,
                              void* d_out, int out_size) {
    const float* node_feat = (const float*)d_in[0];
    const float* net_feat  = (const float*)d_in[1];
    const float* pin_feat  = (const float*)d_in[2];
    const float* edge_feat = (const float*)d_in[3];
    const float* topo_w    = (const float*)d_in[4];
    const float* topo_b    = (const float*)d_in[5];
    const float* geom_w    = (const float*)d_in[6];
    const float* geom_b    = (const float*)d_in[7];
    const float* gc_w      = (const float*)d_in[8];
    const float* gc_b      = (const float*)d_in[9];
    const float* pinned_b  = (const float*)d_in[10];
    const float* near_b    = (const float*)d_in[11];
    const int* pins_src    = (const int*)d_in[12];
    const int* pins_dst    = (const int*)d_in[13];
    const int* pinned_src  = (const int*)d_in[14];
    const int* pinned_dst  = (const int*)d_in[15];
    const int* near_src    = (const int*)d_in[16];
    const int* near_dst    = (const int*)d_in[17];
    float* out = (float*)d_out;

    cudaFuncSetAttribute(k_nnconv_mma, cudaFuncAttributeMaxDynamicSharedMemorySize, SM_TOT);

    float *accp, *accn, *btp, *btn;
    uint2 *fhp, *fhn;
    cudaGetSymbolAddress((void**)&accp, g_accp);
    cudaGetSymbolAddress((void**)&accn, g_accn);
    cudaGetSymbolAddress((void**)&btp,  g_btp);
    cudaGetSymbolAddress((void**)&btn,  g_btn);
    cudaGetSymbolAddress((void**)&fhp,  g_fh_p);
    cudaGetSymbolAddress((void**)&fhn,  g_fh_n);

    // Fork-join concurrency: side stream runs the pins-relation chain while the
    // origin stream runs the NNConv chain.
    cudaStream_t s2;
    cudaStreamCreateWithFlags(&s2, cudaStreamNonBlocking);
    cudaEvent_t evFork, evZero, evDeg, evJoin;
    cudaEventCreateWithFlags(&evFork, cudaEventDisableTiming);
    cudaEventCreateWithFlags(&evZero, cudaEventDisableTiming);
    cudaEventCreateWithFlags(&evDeg,  cudaEventDisableTiming);
    cudaEventCreateWithFlags(&evJoin, cudaEventDisableTiming);

    cudaEventRecord(evFork, 0);
    cudaStreamWaitEvent(s2, evFork, 0);

    // --- side stream: zero + degrees + pins relation ---
    k_zero<<<512, 256, 0, s2>>>();
    cudaEventRecord(evZero, s2);
    k_deg<<<(NEDGE + 255) / 256, 256, 0, s2>>>(pins_src, pins_dst, pinned_dst, near_dst);
    cudaEventRecord(evDeg, s2);
    k_pins<<<(NEDGE * 8 + 255) / 256, 256, 0, s2>>>(node_feat, pins_src, pins_dst);
    k_netout<<<(N_NET * HD + 255) / 256, 256, 0, s2>>>(gc_w, gc_b, out);
    cudaEventRecord(evJoin, s2);

    // --- origin stream: fragment/bias prep + NNConv + final ---
    k_wprep<<<(2 * NFRAG + 255) / 256, 256>>>(topo_w, geom_w, fhp, fhn);
    k_bterm<<<((N_NET + N_NODE) * HD + 255) / 256, 256>>>(net_feat, topo_b,
                                                          node_feat, geom_b);
    cudaStreamWaitEvent(0, evZero, 0);   // acc buffers zeroed
    dim3 grid(GRIDX, 2);
    k_nnconv_mma<<<grid, 256, SM_TOT>>>(net_feat,  pin_feat,  pinned_src, pinned_dst,
                                        fhp, btp, accp,
                                        node_feat, edge_feat, near_src,  near_dst,
                                        fhn, btn, accn);
    cudaStreamWaitEvent(0, evDeg, 0);    // g_deg_p / g_deg_n ready
    k_final<<<(N_NODE * HD + 255) / 256, 256>>>(pinned_b, near_b, out);
    cudaStreamWaitEvent(0, evJoin, 0);   // join side stream (net_out part of out)
}

// round 13
// speedup vs baseline: 1.1247x; 1.0184x over previous
#include <cuda_runtime.h>
#include <cuda_fp16.h>
#include <math.h>
#include <stdint.h>

#define N_NODE 80000
#define N_NET  20000
#define NEDGE  150000
#define HD     32
#define HE     16

#define TILE_M 128
#define NTILES ((NEDGE + TILE_M - 1) / TILE_M)   // 1172
#define GRIDX  222                                // x2 relations = 444 CTAs = 148 SMs * 3
#define NFRAG  (HD * 4 * 32)                      // 4096 fragment slots (i, nb, lane)

// smem layout (bytes)
#define NF_STRIDE 33
#define NF_BYTES  (TILE_M * NF_STRIDE * 4)        // 16896 (u32 half2-dup per element)
#define FH_OFF    NF_BYTES
#define SM_TOT    (NF_BYTES + NFRAG * 8)          // 49664

typedef unsigned int u32;

// ---------------- helpers ----------------
__device__ __forceinline__ u32 f16pair(float lo, float hi) {
    __half2 h = __floats2half2_rn(lo, hi);        // x=lo, y=hi
    return *reinterpret_cast<u32*>(&h);
}
__device__ __forceinline__ u32 half2dup(float v) {
    __half h = __float2half_rn(v);
    u32 hu = *reinterpret_cast<unsigned short*>(&h);
    return hu | (hu << 16);
}
__device__ __forceinline__ u32 hmul2u(u32 a, u32 b) {
    __half2 r = __hmul2(*reinterpret_cast<__half2*>(&a), *reinterpret_cast<__half2*>(&b));
    return *reinterpret_cast<u32*>(&r);
}
__device__ __forceinline__ void mma_f16(float* d, u32 a0, u32 a1, u32 a2, u32 a3,
                                        u32 b0, u32 b1) {
    asm volatile(
        "mma.sync.aligned.m16n8k16.row.col.f32.f16.f16.f32 "
        "{%0,%1,%2,%3}, {%4,%5,%6,%7}, {%8,%9}, {%0,%1,%2,%3};"
        : "+f"(d[0]), "+f"(d[1]), "+f"(d[2]), "+f"(d[3])
        : "r"(a0), "r"(a1), "r"(a2), "r"(a3), "r"(b0), "r"(b1));
}
__device__ __forceinline__ void red_v4(float* p, float a, float b, float c, float d) {
    asm volatile("red.global.add.v4.f32 [%0], {%1, %2, %3, %4};"
                 :: "l"(p), "f"(a), "f"(b), "f"(c), "f"(d) : "memory");
}

// ---- scratch (device globals; no allocation allowed) ----
__device__ float g_deg_out[N_NODE];
__device__ float g_deg_in [N_NET];
__device__ float g_deg_p  [N_NODE];
__device__ float g_deg_n  [N_NODE];
__device__ __align__(16) float g_agg [N_NET * HD];
__device__ __align__(16) float g_accp[N_NODE * HD];
__device__ __align__(16) float g_accn[N_NODE * HD];
__device__ __align__(16) float g_btp [N_NET  * HD];
__device__ __align__(16) float g_btn [N_NODE * HD];
__device__ __align__(16) uint2 g_fh_p[NFRAG];
__device__ __align__(16) uint2 g_fh_n[NFRAG];

// ---------------------------------------------------------------------------
__global__ void k_zero() {
    int stride = gridDim.x * blockDim.x;
    int i0 = blockIdx.x * blockDim.x + threadIdx.x;
    const float4 z = make_float4(0.f, 0.f, 0.f, 0.f);
    for (int j = i0; j < N_NODE / 4; j += stride) {
        reinterpret_cast<float4*>(g_deg_out)[j] = z;
        reinterpret_cast<float4*>(g_deg_p)[j] = z;
        reinterpret_cast<float4*>(g_deg_n)[j] = z;
    }
    for (int j = i0; j < N_NET / 4; j += stride) reinterpret_cast<float4*>(g_deg_in)[j] = z;
    for (int j = i0; j < N_NET * HD / 4; j += stride) reinterpret_cast<float4*>(g_agg)[j] = z;
    for (int j = i0; j < N_NODE * HD / 4; j += stride) {
        reinterpret_cast<float4*>(g_accp)[j] = z;
        reinterpret_cast<float4*>(g_accn)[j] = z;
    }
}

// ---------------------------------------------------------------------------
__global__ void k_deg(const int* __restrict__ ps, const int* __restrict__ pd,
                      const int* __restrict__ pnd, const int* __restrict__ nrd) {
    int e = blockIdx.x * blockDim.x + threadIdx.x;
    if (e >= NEDGE) return;
    atomicAdd(&g_deg_out[ps[e]],  1.f);
    atomicAdd(&g_deg_in [pd[e]],  1.f);
    atomicAdd(&g_deg_p  [pnd[e]], 1.f);
    atomicAdd(&g_deg_n  [nrd[e]], 1.f);
}

// ---------------------------------------------------------------------------
// pins aggregation with vector reductions: one thread per (edge, quarter-row)
__global__ void k_pins(const float* __restrict__ nodef,
                       const int* __restrict__ src, const int* __restrict__ dst) {
    int t = blockIdx.x * blockDim.x + threadIdx.x;
    if (t >= NEDGE * 8) return;
    int e = t >> 3, q = t & 7;
    int s = src[e];
    float nrm = rsqrtf(fmaxf(g_deg_out[s], 1.f));
    float4 v = reinterpret_cast<const float4*>(nodef + (size_t)s * HD)[q];
    red_v4(g_agg + (size_t)dst[e] * HD + q * 4,
           v.x * nrm, v.y * nrm, v.z * nrm, v.w * nrm);
}

// ---------------------------------------------------------------------------
__global__ void k_netout(const float* __restrict__ gcw, const float* __restrict__ gcb,
                         float* __restrict__ out) {
    int t = blockIdx.x * blockDim.x + threadIdx.x;
    if (t >= N_NET * HD) return;
    int n = t >> 5, o = t & 31;
    float nrm = rsqrtf(fmaxf(g_deg_in[n], 1.f));
    float a = 0.f;
    #pragma unroll
    for (int d = 0; d < HD; d++)
        a = fmaf(g_agg[n * HD + d], gcw[d * HD + o], a);
    out[(size_t)N_NODE * HD + t] = a * nrm + gcb[o];
}

// ---------------------------------------------------------------------------
// Precompute fp16 B fragments for BOTH relations (m16n8k16 .col layout).
// Conflict-free layout: slot = (i*4+nb)*32 + lane (lane stride 8 B, LDS.64)
__global__ void k_wprep(const float* __restrict__ w0, const float* __restrict__ w1,
                        uint2* __restrict__ fh0, uint2* __restrict__ fh1) {
    int gidx = blockIdx.x * blockDim.x + threadIdx.x;
    if (gidx >= 2 * NFRAG) return;
    int rel = gidx >= NFRAG;
    int idx = gidx - rel * NFRAG;
    const float* w = rel ? w1 : w0;
    uint2* fh = rel ? fh1 : fh0;
    int lane = idx & 31, nb = (idx >> 5) & 3, i = idx >> 7;
    int o = nb * 8 + (lane >> 2);
    int k0 = (lane & 3) * 2;
    const float* row = w + ((size_t)i * HD + o) * HE;
    fh[idx] = make_uint2(f16pair(row[k0],     row[k0 + 1]),
                         f16pair(row[k0 + 8], row[k0 + 9]));
}

// ---------------------------------------------------------------------------
// Exact bias term tables for both relations in one launch.
__global__ void k_bterm(const float* __restrict__ netf, const float* __restrict__ tb,
                        const float* __restrict__ nodef, const float* __restrict__ gb) {
    int t = blockIdx.x * blockDim.x + threadIdx.x;
    if (t >= (N_NET + N_NODE) * HD) return;
    const float* feat; const float* b; float* out; int row;
    if (t < N_NET * HD) {
        feat = netf; b = tb; out = g_btp; row = t >> 5;
    } else {
        t -= N_NET * HD;
        feat = nodef; b = gb; out = g_btn; row = t >> 5;
    }
    int o = t & 31;
    float a = 0.f;
    #pragma unroll
    for (int i = 0; i < HD; i++)
        a = fmaf(feat[(size_t)row * HD + i], b[i * HD + o], a);
    out[(size_t)row * HD + o] = a;
}

// ---------------------------------------------------------------------------
// Fused NNConv, single-pass fp16 with HMUL2 A-fragments (conflict-free B).
// nf stored as duplicated half2 in smem (float4 gather); pf half2-packed/tile.
// Epilogue: lane pairs combine via shfl_xor(1) -> even lanes issue red.v4.
__global__ void __launch_bounds__(256, 3)
k_nnconv_mma(const float* __restrict__ sf0, const float* __restrict__ ef0,
             const int* __restrict__ src0, const int* __restrict__ dst0,
             const uint2* __restrict__ gfh0, const float* __restrict__ bt0,
             float* __restrict__ acc0,
             const float* __restrict__ sf1, const float* __restrict__ ef1,
             const int* __restrict__ src1, const int* __restrict__ dst1,
             const uint2* __restrict__ gfh1, const float* __restrict__ bt1,
             float* __restrict__ acc1) {
    extern __shared__ char smem[];
    u32* nf_s = (u32*)smem;                        // half2-dup per (row, i)
    uint2* fh_s = (uint2*)(smem + FH_OFF);
    int tid = threadIdx.x;
    int rel = blockIdx.y;

    const float* srcfeat = rel ? sf1 : sf0;
    const float* efeat   = rel ? ef1 : ef0;
    const int* src       = rel ? src1 : src0;
    const int* dst       = rel ? dst1 : dst0;
    const uint2* gfh     = rel ? gfh1 : gfh0;
    const float* bterm   = rel ? bt1 : bt0;
    float* acc           = rel ? acc1 : acc0;

    // copy B fragments (32 KB) into smem once
    {
        const uint4* s1 = (const uint4*)gfh;
        uint4* d1 = (uint4*)fh_s;
        #pragma unroll
        for (int q = 0; q < (NFRAG * 8 / 16) / 256; q++)
            d1[q * 256 + tid] = s1[q * 256 + tid];
    }

    int lane = tid & 31, wid = tid >> 5;
    int r0 = lane >> 2, c0 = (lane & 3) * 2;
    int wr = wid * 16;
    bool evenlane = ((lane & 1) == 0);
    int q0 = (lane & 3) * 2;        // 0,2,4,6 ; even lanes have q0 in {0,4}

    #pragma unroll 1
    for (int tile = blockIdx.x; tile < NTILES; tile += GRIDX) {
        int base = tile * TILE_M;

        __syncthreads();   // protect nf_s reuse (and fragment copy on first iter)
        // float4 gather: 4 iterations, one quad of a row per thread per iter
        #pragma unroll
        for (int it = 0; it < 4; it++) {
            int idx = it * 256 + tid;            // < TILE_M * 8
            int row = idx >> 3, q = idx & 7;
            int e = base + row;
            float4 v = make_float4(0.f, 0.f, 0.f, 0.f);
            if (e < NEDGE)
                v = *(const float4*)(srcfeat + (size_t)src[e] * HD + q * 4);
            u32* p = nf_s + row * NF_STRIDE + q * 4;
            p[0] = half2dup(v.x); p[1] = half2dup(v.y);
            p[2] = half2dup(v.z); p[3] = half2dup(v.w);
        }
        __syncthreads();

        int e0 = base + wr + r0;
        int e1 = e0 + 8;
        bool l0 = (e0 < NEDGE), l1 = (e1 < NEDGE);

        u32 pf0a = 0, pf0b = 0, pf1a = 0, pf1b = 0;   // half2 {pf[c0],pf[c0+1]}, {+8}
        if (l0) {
            float2 q = *(const float2*)(efeat + (size_t)e0 * HE + c0);
            pf0a = f16pair(q.x, q.y);
            q = *(const float2*)(efeat + (size_t)e0 * HE + c0 + 8);
            pf0b = f16pair(q.x, q.y);
        }
        if (l1) {
            float2 q = *(const float2*)(efeat + (size_t)e1 * HE + c0);
            pf1a = f16pair(q.x, q.y);
            q = *(const float2*)(efeat + (size_t)e1 * HE + c0 + 8);
            pf1b = f16pair(q.x, q.y);
        }

        float d[4][4];
        #pragma unroll
        for (int nb = 0; nb < 4; nb++)
            #pragma unroll
            for (int q = 0; q < 4; q++) d[nb][q] = 0.f;

        #pragma unroll 4
        for (int i = 0; i < HD; i++) {
            u32 f0d = nf_s[(wr + r0) * NF_STRIDE + i];
            u32 f1d = nf_s[(wr + r0 + 8) * NF_STRIDE + i];
            u32 ah0 = hmul2u(f0d, pf0a);
            u32 ah1 = hmul2u(f1d, pf1a);
            u32 ah2 = hmul2u(f0d, pf0b);
            u32 ah3 = hmul2u(f1d, pf1b);
            #pragma unroll
            for (int nb = 0; nb < 4; nb++) {
                uint2 bh = fh_s[(i * 4 + nb) * 32 + lane];
                mma_f16(d[nb], ah0, ah1, ah2, ah3, bh.x, bh.y);
            }
        }

        // epilogue: pair lanes (lane, lane^1) -> even lane writes red.v4 of 4 cols
        if (l0) {
            int s0 = src[e0], dn0 = dst[e0];
            const float* bt = bterm + (size_t)s0 * HD;
            float* ap = acc + (size_t)dn0 * HD;
            #pragma unroll
            for (int nb = 0; nb < 4; nb++) {
                float p0 = __shfl_xor_sync(0xffffffffu, d[nb][0], 1);
                float p1 = __shfl_xor_sync(0xffffffffu, d[nb][1], 1);
                if (evenlane) {
                    int o = nb * 8 + q0;            // multiple of 4
                    float4 bq = *(const float4*)(bt + o);
                    red_v4(ap + o, d[nb][0] + bq.x, d[nb][1] + bq.y,
                                   p0 + bq.z,       p1 + bq.w);
                }
            }
        }
        if (l1) {
            int s1i = src[e1], dn1 = dst[e1];
            const float* bt = bterm + (size_t)s1i * HD;
            float* ap = acc + (size_t)dn1 * HD;
            #pragma unroll
            for (int nb = 0; nb < 4; nb++) {
                float p2 = __shfl_xor_sync(0xffffffffu, d[nb][2], 1);
                float p3 = __shfl_xor_sync(0xffffffffu, d[nb][3], 1);
                if (evenlane) {
                    int o = nb * 8 + q0;
                    float4 bq = *(const float4*)(bt + o);
                    red_v4(ap + o, d[nb][2] + bq.x, d[nb][3] + bq.y,
                                   p2 + bq.z,       p3 + bq.w);
                }
            }
        }
    }
}

// ---------------------------------------------------------------------------
__global__ void k_final(const float* __restrict__ pb, const float* __restrict__ nb,
                        float* __restrict__ out) {
    int t = blockIdx.x * blockDim.x + threadIdx.x;
    if (t >= N_NODE * HD) return;
    int n = t >> 5, o = t & 31;
    float p = g_accp[t] / fmaxf(g_deg_p[n], 1.f) + pb[o];
    float q = g_accn[t] / fmaxf(g_deg_n[n], 1.f) + nb[o];
    out[t] = fmaxf(p, q);
}

// ---------------------------------------------------------------------------
extern "C" void kernel_launch(void* const* d_in, const int* in_sizes, int n_in,
                              void* d_out, int out_size) {
    const float* node_feat = (const float*)d_in[0];
    const float* net_feat  = (const float*)d_in[1];
    const float* pin_feat  = (const float*)d_in[2];
    const float* edge_feat = (const float*)d_in[3];
    const float* topo_w    = (const float*)d_in[4];
    const float* topo_b    = (const float*)d_in[5];
    const float* geom_w    = (const float*)d_in[6];
    const float* geom_b    = (const float*)d_in[7];
    const float* gc_w      = (const float*)d_in[8];
    const float* gc_b      = (const float*)d_in[9];
    const float* pinned_b  = (const float*)d_in[10];
    const float* near_b    = (const float*)d_in[11];
    const int* pins_src    = (const int*)d_in[12];
    const int* pins_dst    = (const int*)d_in[13];
    const int* pinned_src  = (const int*)d_in[14];
    const int* pinned_dst  = (const int*)d_in[15];
    const int* near_src    = (const int*)d_in[16];
    const int* near_dst    = (const int*)d_in[17];
    float* out = (float*)d_out;

    cudaFuncSetAttribute(k_nnconv_mma, cudaFuncAttributeMaxDynamicSharedMemorySize, SM_TOT);

    float *accp, *accn, *btp, *btn;
    uint2 *fhp, *fhn;
    cudaGetSymbolAddress((void**)&accp, g_accp);
    cudaGetSymbolAddress((void**)&accn, g_accn);
    cudaGetSymbolAddress((void**)&btp,  g_btp);
    cudaGetSymbolAddress((void**)&btn,  g_btn);
    cudaGetSymbolAddress((void**)&fhp,  g_fh_p);
    cudaGetSymbolAddress((void**)&fhn,  g_fh_n);

    // Fork-join concurrency: side stream runs the pins-relation chain while the
    // origin stream runs the NNConv chain.
    cudaStream_t s2;
    cudaStreamCreateWithFlags(&s2, cudaStreamNonBlocking);
    cudaEvent_t evFork, evZero, evDeg, evJoin;
    cudaEventCreateWithFlags(&evFork, cudaEventDisableTiming);
    cudaEventCreateWithFlags(&evZero, cudaEventDisableTiming);
    cudaEventCreateWithFlags(&evDeg,  cudaEventDisableTiming);
    cudaEventCreateWithFlags(&evJoin, cudaEventDisableTiming);

    cudaEventRecord(evFork, 0);
    cudaStreamWaitEvent(s2, evFork, 0);

    // --- side stream: zero + degrees + pins relation ---
    k_zero<<<512, 256, 0, s2>>>();
    cudaEventRecord(evZero, s2);
    k_deg<<<(NEDGE + 255) / 256, 256, 0, s2>>>(pins_src, pins_dst, pinned_dst, near_dst);
    cudaEventRecord(evDeg, s2);
    k_pins<<<(NEDGE * 8 + 255) / 256, 256, 0, s2>>>(node_feat, pins_src, pins_dst);
    k_netout<<<(N_NET * HD + 255) / 256, 256, 0, s2>>>(gc_w, gc_b, out);
    cudaEventRecord(evJoin, s2);

    // --- origin stream: fragment/bias prep + NNConv + final ---
    k_wprep<<<(2 * NFRAG + 255) / 256, 256>>>(topo_w, geom_w, fhp, fhn);
    k_bterm<<<((N_NET + N_NODE) * HD + 255) / 256, 256>>>(net_feat, topo_b,
                                                          node_feat, geom_b);
    cudaStreamWaitEvent(0, evZero, 0);   // acc buffers zeroed
    dim3 grid(GRIDX, 2);
    k_nnconv_mma<<<grid, 256, SM_TOT>>>(net_feat,  pin_feat,  pinned_src, pinned_dst,
                                        fhp, btp, accp,
                                        node_feat, edge_feat, near_src,  near_dst,
                                        fhn, btn, accn);
    cudaStreamWaitEvent(0, evDeg, 0);    // g_deg_p / g_deg_n ready
    k_final<<<(N_NODE * HD + 255) / 256, 256>>>(pinned_b, near_b, out);
    cudaStreamWaitEvent(0, evJoin, 0);   // join side stream (net_out part of out)
}

// round 14
// speedup vs baseline: 1.2311x; 1.0947x over previous
#include <cuda_runtime.h>
#include <cuda_fp16.h>
#include <math.h>
#include <stdint.h>

#define N_NODE 80000
#define N_NET  20000
#define NEDGE  150000
#define HD     32
#define HE     16

#define TILE_M 128
#define NTILES ((NEDGE + TILE_M - 1) / TILE_M)   // 1172
#define GRIDX  296                                // x2 relations = 592 CTAs = 148 SMs * 4
#define NFRAG  (HD * 4 * 32)                      // 4096 fragment slots (i, nb, lane)

// smem layout (bytes)
#define NF_STRIDE 33
#define NF_BYTES  (TILE_M * NF_STRIDE * 4)        // 16896 (u32 half2-dup per element)
#define FH_OFF    NF_BYTES
#define SM_TOT    (NF_BYTES + NFRAG * 8)          // 49664

typedef unsigned int u32;

// ---------------- helpers ----------------
__device__ __forceinline__ u32 f16pair(float lo, float hi) {
    __half2 h = __floats2half2_rn(lo, hi);        // x=lo, y=hi
    return *reinterpret_cast<u32*>(&h);
}
__device__ __forceinline__ u32 half2dup(float v) {
    __half h = __float2half_rn(v);
    u32 hu = *reinterpret_cast<unsigned short*>(&h);
    return hu | (hu << 16);
}
__device__ __forceinline__ u32 hmul2u(u32 a, u32 b) {
    __half2 r = __hmul2(*reinterpret_cast<__half2*>(&a), *reinterpret_cast<__half2*>(&b));
    return *reinterpret_cast<u32*>(&r);
}
__device__ __forceinline__ void mma_f16(float* d, u32 a0, u32 a1, u32 a2, u32 a3,
                                        u32 b0, u32 b1) {
    asm volatile(
        "mma.sync.aligned.m16n8k16.row.col.f32.f16.f16.f32 "
        "{%0,%1,%2,%3}, {%4,%5,%6,%7}, {%8,%9}, {%0,%1,%2,%3};"
        : "+f"(d[0]), "+f"(d[1]), "+f"(d[2]), "+f"(d[3])
        : "r"(a0), "r"(a1), "r"(a2), "r"(a3), "r"(b0), "r"(b1));
}
__device__ __forceinline__ void red_v4(float* p, float a, float b, float c, float d) {
    asm volatile("red.global.add.v4.f32 [%0], {%1, %2, %3, %4};"
                 :: "l"(p), "f"(a), "f"(b), "f"(c), "f"(d) : "memory");
}

// ---- scratch (device globals; no allocation allowed) ----
__device__ float g_deg_out[N_NODE];
__device__ float g_deg_in [N_NET];
__device__ float g_deg_p  [N_NODE];
__device__ float g_deg_n  [N_NODE];
__device__ __align__(16) float g_agg [N_NET * HD];
__device__ __align__(16) float g_accp[N_NODE * HD];
__device__ __align__(16) float g_accn[N_NODE * HD];
__device__ __align__(16) float g_btp [N_NET  * HD];
__device__ __align__(16) float g_btn [N_NODE * HD];
__device__ __align__(16) uint2 g_fh_p[NFRAG];
__device__ __align__(16) uint2 g_fh_n[NFRAG];

// ---------------------------------------------------------------------------
__global__ void k_zero() {
    int stride = gridDim.x * blockDim.x;
    int i0 = blockIdx.x * blockDim.x + threadIdx.x;
    const float4 z = make_float4(0.f, 0.f, 0.f, 0.f);
    for (int j = i0; j < N_NODE / 4; j += stride) {
        reinterpret_cast<float4*>(g_deg_out)[j] = z;
        reinterpret_cast<float4*>(g_deg_p)[j] = z;
        reinterpret_cast<float4*>(g_deg_n)[j] = z;
    }
    for (int j = i0; j < N_NET / 4; j += stride) reinterpret_cast<float4*>(g_deg_in)[j] = z;
    for (int j = i0; j < N_NET * HD / 4; j += stride) reinterpret_cast<float4*>(g_agg)[j] = z;
    for (int j = i0; j < N_NODE * HD / 4; j += stride) {
        reinterpret_cast<float4*>(g_accp)[j] = z;
        reinterpret_cast<float4*>(g_accn)[j] = z;
    }
}

// ---------------------------------------------------------------------------
__global__ void k_deg(const int* __restrict__ ps, const int* __restrict__ pd,
                      const int* __restrict__ pnd, const int* __restrict__ nrd) {
    int e = blockIdx.x * blockDim.x + threadIdx.x;
    if (e >= NEDGE) return;
    atomicAdd(&g_deg_out[ps[e]],  1.f);
    atomicAdd(&g_deg_in [pd[e]],  1.f);
    atomicAdd(&g_deg_p  [pnd[e]], 1.f);
    atomicAdd(&g_deg_n  [nrd[e]], 1.f);
}

// ---------------------------------------------------------------------------
// pins aggregation with vector reductions: one thread per (edge, quarter-row)
__global__ void k_pins(const float* __restrict__ nodef,
                       const int* __restrict__ src, const int* __restrict__ dst) {
    int t = blockIdx.x * blockDim.x + threadIdx.x;
    if (t >= NEDGE * 8) return;
    int e = t >> 3, q = t & 7;
    int s = src[e];
    float nrm = rsqrtf(fmaxf(g_deg_out[s], 1.f));
    float4 v = reinterpret_cast<const float4*>(nodef + (size_t)s * HD)[q];
    red_v4(g_agg + (size_t)dst[e] * HD + q * 4,
           v.x * nrm, v.y * nrm, v.z * nrm, v.w * nrm);
}

// ---------------------------------------------------------------------------
__global__ void k_netout(const float* __restrict__ gcw, const float* __restrict__ gcb,
                         float* __restrict__ out) {
    int t = blockIdx.x * blockDim.x + threadIdx.x;
    if (t >= N_NET * HD) return;
    int n = t >> 5, o = t & 31;
    float nrm = rsqrtf(fmaxf(g_deg_in[n], 1.f));
    float a = 0.f;
    #pragma unroll
    for (int d = 0; d < HD; d++)
        a = fmaf(g_agg[n * HD + d], gcw[d * HD + o], a);
    out[(size_t)N_NODE * HD + t] = a * nrm + gcb[o];
}

// ---------------------------------------------------------------------------
// Precompute fp16 B fragments for BOTH relations (m16n8k16 .col layout).
// Conflict-free layout: slot = (i*4+nb)*32 + lane (lane stride 8 B, LDS.64)
__global__ void k_wprep(const float* __restrict__ w0, const float* __restrict__ w1,
                        uint2* __restrict__ fh0, uint2* __restrict__ fh1) {
    int gidx = blockIdx.x * blockDim.x + threadIdx.x;
    if (gidx >= 2 * NFRAG) return;
    int rel = gidx >= NFRAG;
    int idx = gidx - rel * NFRAG;
    const float* w = rel ? w1 : w0;
    uint2* fh = rel ? fh1 : fh0;
    int lane = idx & 31, nb = (idx >> 5) & 3, i = idx >> 7;
    int o = nb * 8 + (lane >> 2);
    int k0 = (lane & 3) * 2;
    const float* row = w + ((size_t)i * HD + o) * HE;
    fh[idx] = make_uint2(f16pair(row[k0],     row[k0 + 1]),
                         f16pair(row[k0 + 8], row[k0 + 9]));
}

// ---------------------------------------------------------------------------
// Exact bias term tables for both relations in one launch.
__global__ void k_bterm(const float* __restrict__ netf, const float* __restrict__ tb,
                        const float* __restrict__ nodef, const float* __restrict__ gb) {
    int t = blockIdx.x * blockDim.x + threadIdx.x;
    if (t >= (N_NET + N_NODE) * HD) return;
    const float* feat; const float* b; float* out; int row;
    if (t < N_NET * HD) {
        feat = netf; b = tb; out = g_btp; row = t >> 5;
    } else {
        t -= N_NET * HD;
        feat = nodef; b = gb; out = g_btn; row = t >> 5;
    }
    int o = t & 31;
    float a = 0.f;
    #pragma unroll
    for (int i = 0; i < HD; i++)
        a = fmaf(feat[(size_t)row * HD + i], b[i * HD + o], a);
    out[(size_t)row * HD + o] = a;
}

// ---------------------------------------------------------------------------
// Fused NNConv, single-pass fp16 with HMUL2 A-fragments (conflict-free B).
// 4 CTAs/SM (64-reg cap) + grid sized to exactly 4 waves of work per SM.
__global__ void __launch_bounds__(256, 4)
k_nnconv_mma(const float* __restrict__ sf0, const float* __restrict__ ef0,
             const int* __restrict__ src0, const int* __restrict__ dst0,
             const uint2* __restrict__ gfh0, const float* __restrict__ bt0,
             float* __restrict__ acc0,
             const float* __restrict__ sf1, const float* __restrict__ ef1,
             const int* __restrict__ src1, const int* __restrict__ dst1,
             const uint2* __restrict__ gfh1, const float* __restrict__ bt1,
             float* __restrict__ acc1) {
    extern __shared__ char smem[];
    u32* nf_s = (u32*)smem;                        // half2-dup per (row, i)
    uint2* fh_s = (uint2*)(smem + FH_OFF);
    int tid = threadIdx.x;
    int rel = blockIdx.y;

    const float* srcfeat = rel ? sf1 : sf0;
    const float* efeat   = rel ? ef1 : ef0;
    const int* src       = rel ? src1 : src0;
    const int* dst       = rel ? dst1 : dst0;
    const uint2* gfh     = rel ? gfh1 : gfh0;
    const float* bterm   = rel ? bt1 : bt0;
    float* acc           = rel ? acc1 : acc0;

    // copy B fragments (32 KB) into smem once
    {
        const uint4* s1 = (const uint4*)gfh;
        uint4* d1 = (uint4*)fh_s;
        #pragma unroll
        for (int q = 0; q < (NFRAG * 8 / 16) / 256; q++)
            d1[q * 256 + tid] = s1[q * 256 + tid];
    }

    int lane = tid & 31, wid = tid >> 5;
    int r0 = lane >> 2, c0 = (lane & 3) * 2;
    int wr = wid * 16;
    bool evenlane = ((lane & 1) == 0);
    int q0 = (lane & 3) * 2;        // 0,2,4,6 ; even lanes have q0 in {0,4}

    #pragma unroll 1
    for (int tile = blockIdx.x; tile < NTILES; tile += GRIDX) {
        int base = tile * TILE_M;

        __syncthreads();   // protect nf_s reuse (and fragment copy on first iter)
        // float4 gather: 4 iterations, one quad of a row per thread per iter
        #pragma unroll
        for (int it = 0; it < 4; it++) {
            int idx = it * 256 + tid;            // < TILE_M * 8
            int row = idx >> 3, q = idx & 7;
            int e = base + row;
            float4 v = make_float4(0.f, 0.f, 0.f, 0.f);
            if (e < NEDGE)
                v = *(const float4*)(srcfeat + (size_t)src[e] * HD + q * 4);
            u32* p = nf_s + row * NF_STRIDE + q * 4;
            p[0] = half2dup(v.x); p[1] = half2dup(v.y);
            p[2] = half2dup(v.z); p[3] = half2dup(v.w);
        }
        __syncthreads();

        int e0 = base + wr + r0;
        int e1 = e0 + 8;
        bool l0 = (e0 < NEDGE), l1 = (e1 < NEDGE);

        u32 pf0a = 0, pf0b = 0, pf1a = 0, pf1b = 0;   // half2 {pf[c0],pf[c0+1]}, {+8}
        if (l0) {
            float2 q = *(const float2*)(efeat + (size_t)e0 * HE + c0);
            pf0a = f16pair(q.x, q.y);
            q = *(const float2*)(efeat + (size_t)e0 * HE + c0 + 8);
            pf0b = f16pair(q.x, q.y);
        }
        if (l1) {
            float2 q = *(const float2*)(efeat + (size_t)e1 * HE + c0);
            pf1a = f16pair(q.x, q.y);
            q = *(const float2*)(efeat + (size_t)e1 * HE + c0 + 8);
            pf1b = f16pair(q.x, q.y);
        }

        float d[4][4];
        #pragma unroll
        for (int nb = 0; nb < 4; nb++)
            #pragma unroll
            for (int q = 0; q < 4; q++) d[nb][q] = 0.f;

        #pragma unroll 4
        for (int i = 0; i < HD; i++) {
            u32 f0d = nf_s[(wr + r0) * NF_STRIDE + i];
            u32 f1d = nf_s[(wr + r0 + 8) * NF_STRIDE + i];
            u32 ah0 = hmul2u(f0d, pf0a);
            u32 ah1 = hmul2u(f1d, pf1a);
            u32 ah2 = hmul2u(f0d, pf0b);
            u32 ah3 = hmul2u(f1d, pf1b);
            #pragma unroll
            for (int nb = 0; nb < 4; nb++) {
                uint2 bh = fh_s[(i * 4 + nb) * 32 + lane];
                mma_f16(d[nb], ah0, ah1, ah2, ah3, bh.x, bh.y);
            }
        }

        // epilogue: pair lanes (lane, lane^1) -> even lane writes red.v4 of 4 cols
        if (l0) {
            int s0 = src[e0], dn0 = dst[e0];
            const float* bt = bterm + (size_t)s0 * HD;
            float* ap = acc + (size_t)dn0 * HD;
            #pragma unroll
            for (int nb = 0; nb < 4; nb++) {
                float p0 = __shfl_xor_sync(0xffffffffu, d[nb][0], 1);
                float p1 = __shfl_xor_sync(0xffffffffu, d[nb][1], 1);
                if (evenlane) {
                    int o = nb * 8 + q0;            // multiple of 4
                    float4 bq = *(const float4*)(bt + o);
                    red_v4(ap + o, d[nb][0] + bq.x, d[nb][1] + bq.y,
                                   p0 + bq.z,       p1 + bq.w);
                }
            }
        }
        if (l1) {
            int s1i = src[e1], dn1 = dst[e1];
            const float* bt = bterm + (size_t)s1i * HD;
            float* ap = acc + (size_t)dn1 * HD;
            #pragma unroll
            for (int nb = 0; nb < 4; nb++) {
                float p2 = __shfl_xor_sync(0xffffffffu, d[nb][2], 1);
                float p3 = __shfl_xor_sync(0xffffffffu, d[nb][3], 1);
                if (evenlane) {
                    int o = nb * 8 + q0;
                    float4 bq = *(const float4*)(bt + o);
                    red_v4(ap + o, d[nb][2] + bq.x, d[nb][3] + bq.y,
                                   p2 + bq.z,       p3 + bq.w);
                }
            }
        }
    }
}

// ---------------------------------------------------------------------------
__global__ void k_final(const float* __restrict__ pb, const float* __restrict__ nb,
                        float* __restrict__ out) {
    int t = blockIdx.x * blockDim.x + threadIdx.x;
    if (t >= N_NODE * HD) return;
    int n = t >> 5, o = t & 31;
    float p = g_accp[t] / fmaxf(g_deg_p[n], 1.f) + pb[o];
    float q = g_accn[t] / fmaxf(g_deg_n[n], 1.f) + nb[o];
    out[t] = fmaxf(p, q);
}

// ---------------------------------------------------------------------------
extern "C" void kernel_launch(void* const* d_in, const int* in_sizes, int n_in,
                              void* d_out, int out_size) {
    const float* node_feat = (const float*)d_in[0];
    const float* net_feat  = (const float*)d_in[1];
    const float* pin_feat  = (const float*)d_in[2];
    const float* edge_feat = (const float*)d_in[3];
    const float* topo_w    = (const float*)d_in[4];
    const float* topo_b    = (const float*)d_in[5];
    const float* geom_w    = (const float*)d_in[6];
    const float* geom_b    = (const float*)d_in[7];
    const float* gc_w      = (const float*)d_in[8];
    const float* gc_b      = (const float*)d_in[9];
    const float* pinned_b  = (const float*)d_in[10];
    const float* near_b    = (const float*)d_in[11];
    const int* pins_src    = (const int*)d_in[12];
    const int* pins_dst    = (const int*)d_in[13];
    const int* pinned_src  = (const int*)d_in[14];
    const int* pinned_dst  = (const int*)d_in[15];
    const int* near_src    = (const int*)d_in[16];
    const int* near_dst    = (const int*)d_in[17];
    float* out = (float*)d_out;

    cudaFuncSetAttribute(k_nnconv_mma, cudaFuncAttributeMaxDynamicSharedMemorySize, SM_TOT);

    float *accp, *accn, *btp, *btn;
    uint2 *fhp, *fhn;
    cudaGetSymbolAddress((void**)&accp, g_accp);
    cudaGetSymbolAddress((void**)&accn, g_accn);
    cudaGetSymbolAddress((void**)&btp,  g_btp);
    cudaGetSymbolAddress((void**)&btn,  g_btn);
    cudaGetSymbolAddress((void**)&fhp,  g_fh_p);
    cudaGetSymbolAddress((void**)&fhn,  g_fh_n);

    // Fork-join concurrency: side stream runs the pins-relation chain while the
    // origin stream runs the NNConv chain.
    cudaStream_t s2;
    cudaStreamCreateWithFlags(&s2, cudaStreamNonBlocking);
    cudaEvent_t evFork, evZero, evDeg, evJoin;
    cudaEventCreateWithFlags(&evFork, cudaEventDisableTiming);
    cudaEventCreateWithFlags(&evZero, cudaEventDisableTiming);
    cudaEventCreateWithFlags(&evDeg,  cudaEventDisableTiming);
    cudaEventCreateWithFlags(&evJoin, cudaEventDisableTiming);

    cudaEventRecord(evFork, 0);
    cudaStreamWaitEvent(s2, evFork, 0);

    // --- side stream: zero + degrees + pins relation ---
    k_zero<<<512, 256, 0, s2>>>();
    cudaEventRecord(evZero, s2);
    k_deg<<<(NEDGE + 255) / 256, 256, 0, s2>>>(pins_src, pins_dst, pinned_dst, near_dst);
    cudaEventRecord(evDeg, s2);
    k_pins<<<(NEDGE * 8 + 255) / 256, 256, 0, s2>>>(node_feat, pins_src, pins_dst);
    k_netout<<<(N_NET * HD + 255) / 256, 256, 0, s2>>>(gc_w, gc_b, out);
    cudaEventRecord(evJoin, s2);

    // --- origin stream: fragment/bias prep + NNConv + final ---
    k_wprep<<<(2 * NFRAG + 255) / 256, 256>>>(topo_w, geom_w, fhp, fhn);
    k_bterm<<<((N_NET + N_NODE) * HD + 255) / 256, 256>>>(net_feat, topo_b,
                                                          node_feat, geom_b);
    cudaStreamWaitEvent(0, evZero, 0);   // acc buffers zeroed
    dim3 grid(GRIDX, 2);
    k_nnconv_mma<<<grid, 256, SM_TOT>>>(net_feat,  pin_feat,  pinned_src, pinned_dst,
                                        fhp, btp, accp,
                                        node_feat, edge_feat, near_src,  near_dst,
                                        fhn, btn, accn);
    cudaStreamWaitEvent(0, evDeg, 0);    // g_deg_p / g_deg_n ready
    k_final<<<(N_NODE * HD + 255) / 256, 256>>>(pinned_b, near_b, out);
    cudaStreamWaitEvent(0, evJoin, 0);   // join side stream (net_out part of out)
}